// round 12
// baseline (speedup 1.0000x reference)
#include <cuda_runtime.h>
#include <cuda_fp16.h>
#include <cstdint>
#include <mma.h>

using namespace nvcuda;

// Problem constants
#define DIMC   512
#define N3C    1536
#define MROWS  100352   // 8*256*49
#define WTOK   49
#define NWIN   2048     // 8*256 windows
#define ATT_SCALE 0.17677669529663687f  // 32^-0.5

// ---------------- scratch (static __device__ — no allocations allowed) ----------------
__device__ __half g_xhi[(size_t)MROWS * DIMC];   // 103 MB
__device__ __half g_xlo[(size_t)MROWS * DIMC];   // 103 MB
__device__ __half g_whi[(size_t)DIMC * N3C];     // 1.5 MB
__device__ __half g_wlo[(size_t)DIMC * N3C];     // 1.5 MB
__device__ float  g_qkv[(size_t)MROWS * N3C];    // 616 MB fp32 qkv (bias+scale fused)

// ---------------- cp.async helpers ----------------
__device__ __forceinline__ void cp_async16(void* smem_dst, const void* gmem_src) {
    unsigned int s = (unsigned int)__cvta_generic_to_shared(smem_dst);
    asm volatile("cp.async.ca.shared.global [%0], [%1], 16;\n" :: "r"(s), "l"(gmem_src));
}
__device__ __forceinline__ void cp_async_commit() {
    asm volatile("cp.async.commit_group;\n" ::: "memory");
}
template<int N>
__device__ __forceinline__ void cp_async_wait() {
    asm volatile("cp.async.wait_group %0;\n" :: "n"(N) : "memory");
}

// ---------------- fp32 -> split fp16 (hi + lo) converters ----------------
__global__ void conv_x_kernel(const float* __restrict__ in, int n4) {
    int i = blockIdx.x * blockDim.x + threadIdx.x;
    if (i < n4) {
        float4 v = reinterpret_cast<const float4*>(in)[i];
        __half h0 = __float2half_rn(v.x), h1 = __float2half_rn(v.y);
        __half h2 = __float2half_rn(v.z), h3 = __float2half_rn(v.w);
        __half l0 = __float2half_rn(v.x - __half2float(h0));
        __half l1 = __float2half_rn(v.y - __half2float(h1));
        __half l2 = __float2half_rn(v.z - __half2float(h2));
        __half l3 = __float2half_rn(v.w - __half2float(h3));
        reinterpret_cast<__half2*>(g_xhi)[2 * i]     = __halves2half2(h0, h1);
        reinterpret_cast<__half2*>(g_xhi)[2 * i + 1] = __halves2half2(h2, h3);
        reinterpret_cast<__half2*>(g_xlo)[2 * i]     = __halves2half2(l0, l1);
        reinterpret_cast<__half2*>(g_xlo)[2 * i + 1] = __halves2half2(l2, l3);
    }
}

__global__ void conv_w_kernel(const float* __restrict__ in, int n4) {
    int i = blockIdx.x * blockDim.x + threadIdx.x;
    if (i < n4) {
        float4 v = reinterpret_cast<const float4*>(in)[i];
        __half h0 = __float2half_rn(v.x), h1 = __float2half_rn(v.y);
        __half h2 = __float2half_rn(v.z), h3 = __float2half_rn(v.w);
        __half l0 = __float2half_rn(v.x - __half2float(h0));
        __half l1 = __float2half_rn(v.y - __half2float(h1));
        __half l2 = __float2half_rn(v.z - __half2float(h2));
        __half l3 = __float2half_rn(v.w - __half2float(h3));
        reinterpret_cast<__half2*>(g_whi)[2 * i]     = __halves2half2(h0, h1);
        reinterpret_cast<__half2*>(g_whi)[2 * i + 1] = __halves2half2(h2, h3);
        reinterpret_cast<__half2*>(g_wlo)[2 * i]     = __halves2half2(l0, l1);
        reinterpret_cast<__half2*>(g_wlo)[2 * i + 1] = __halves2half2(l2, l3);
    }
}

// ---------------- QKV GEMM: split-fp16, 2-stage cp.async pipeline ----------------
// [100352,512] x [512,1536] -> [100352,1536] fp32.
// Tile 128x128x32, 8 warps (4M x 2N). q,k blocks (bn<8): 3 MMA passes; v blocks: 1.
// Grid: (bn=12, bm=784) so consecutive blocks share the A tile (L2 reuse).
#define BM 128
#define BN 128
#define BK 32
#define ASTR 48    // halves per A row (96B)
#define BSTR 144   // halves per B row

#define AHI_OFF 0
#define ALO_OFF (BM * ASTR * 2)                     // 12288
#define BHI_OFF (2 * BM * ASTR * 2)                 // 24576
#define BLO_OFF (2 * BM * ASTR * 2 + BK * BSTR * 2) // 33792
#define STG_BYTES (2 * BM * ASTR * 2 + 2 * BK * BSTR * 2)  // 43008
#define GEMM_SMEM_BYTES (2 * STG_BYTES)             // 86016

__global__ void __launch_bounds__(256) qkv_gemm_kernel(const float* __restrict__ bias) {
    extern __shared__ __align__(16) unsigned char gsm[];

    const int tid  = threadIdx.x;
    const int warp = tid >> 5;
    const int lane = tid & 31;
    const int bn = blockIdx.x;  // 12  (fastest -> A tile L2 reuse)
    const int bm = blockIdx.y;  // 784
    const int wm = warp & 3;
    const int wn = warp >> 2;
    const bool doSplit = (bn < 8);   // q,k columns need split precision

    wmma::fragment<wmma::accumulator, 16, 16, 16, float> acc[2][4];
#pragma unroll
    for (int mi = 0; mi < 2; mi++)
#pragma unroll
        for (int ni = 0; ni < 4; ni++)
            wmma::fill_fragment(acc[mi][ni], 0.0f);

    const size_t abase = (size_t)bm * BM * DIMC;

    // Per-stage async load: 512 16B chunks for A (128x32) and B (32x128); 2 per thread.
    auto issue = [&](int kt) {
        unsigned char* st = gsm + (size_t)(kt & 1) * STG_BYTES;
        __half* Ah = reinterpret_cast<__half*>(st + AHI_OFF);
        __half* Al = reinterpret_cast<__half*>(st + ALO_OFF);
        __half* Bh = reinterpret_cast<__half*>(st + BHI_OFF);
        __half* Bl = reinterpret_cast<__half*>(st + BLO_OFF);
        const int k0 = kt * BK;
#pragma unroll
        for (int q = 0; q < 2; q++) {
            const int ch = tid * 2 + q;
            const int ar = ch >> 2, ac = (ch & 3) * 8;
            const size_t ga = abase + (size_t)ar * DIMC + k0 + ac;
            cp_async16(&Ah[ar * ASTR + ac], &g_xhi[ga]);
            const int br = ch >> 4, bc = (ch & 15) * 8;
            const size_t gb = (size_t)(k0 + br) * N3C + bn * BN + bc;
            cp_async16(&Bh[br * BSTR + bc], &g_whi[gb]);
            if (doSplit) {
                cp_async16(&Al[ar * ASTR + ac], &g_xlo[ga]);
                cp_async16(&Bl[br * BSTR + bc], &g_wlo[gb]);
            }
        }
        cp_async_commit();
    };

    issue(0);

    for (int kt = 0; kt < DIMC / BK; kt++) {
        if (kt + 1 < DIMC / BK) {
            issue(kt + 1);
            cp_async_wait<1>();
        } else {
            cp_async_wait<0>();
        }
        __syncthreads();

        unsigned char* st = gsm + (size_t)(kt & 1) * STG_BYTES;
        __half* As_hi = reinterpret_cast<__half*>(st + AHI_OFF);
        __half* As_lo = reinterpret_cast<__half*>(st + ALO_OFF);
        __half* Bs_hi = reinterpret_cast<__half*>(st + BHI_OFF);
        __half* Bs_lo = reinterpret_cast<__half*>(st + BLO_OFF);

#pragma unroll
        for (int kk = 0; kk < 2; kk++) {
            wmma::fragment<wmma::matrix_a, 16, 16, 16, __half, wmma::row_major> af_hi[2], af_lo[2];
            wmma::fragment<wmma::matrix_b, 16, 16, 16, __half, wmma::row_major> bf[4];
#pragma unroll
            for (int mi = 0; mi < 2; mi++)
                wmma::load_matrix_sync(af_hi[mi], &As_hi[(wm * 32 + mi * 16) * ASTR + kk * 16], ASTR);
            if (doSplit) {
#pragma unroll
                for (int mi = 0; mi < 2; mi++)
                    wmma::load_matrix_sync(af_lo[mi], &As_lo[(wm * 32 + mi * 16) * ASTR + kk * 16], ASTR);
            }
#pragma unroll
            for (int ni = 0; ni < 4; ni++)
                wmma::load_matrix_sync(bf[ni], &Bs_hi[(kk * 16) * BSTR + wn * 64 + ni * 16], BSTR);
#pragma unroll
            for (int mi = 0; mi < 2; mi++)
#pragma unroll
                for (int ni = 0; ni < 4; ni++)
                    wmma::mma_sync(acc[mi][ni], af_hi[mi], bf[ni], acc[mi][ni]);
            if (doSplit) {
#pragma unroll
                for (int mi = 0; mi < 2; mi++)
#pragma unroll
                    for (int ni = 0; ni < 4; ni++)
                        wmma::mma_sync(acc[mi][ni], af_lo[mi], bf[ni], acc[mi][ni]);
#pragma unroll
                for (int ni = 0; ni < 4; ni++)
                    wmma::load_matrix_sync(bf[ni], &Bs_lo[(kk * 16) * BSTR + wn * 64 + ni * 16], BSTR);
#pragma unroll
                for (int mi = 0; mi < 2; mi++)
#pragma unroll
                    for (int ni = 0; ni < 4; ni++)
                        wmma::mma_sync(acc[mi][ni], af_hi[mi], bf[ni], acc[mi][ni]);
            }
        }
        __syncthreads();
    }

    // Epilogue: per-warp 16x24 fp32 stage (aliases stage-0 smem), bias+scale, float4 stores
    float* stage = reinterpret_cast<float*>(gsm) + warp * (16 * 24);
    const float scl = (bn < 4) ? ATT_SCALE : 1.0f;
#pragma unroll
    for (int mi = 0; mi < 2; mi++) {
#pragma unroll
        for (int ni = 0; ni < 4; ni++) {
            wmma::store_matrix_sync(stage, acc[mi][ni], 24, wmma::mem_row_major);
            __syncwarp();
            const int gm = bm * BM + wm * 32 + mi * 16;
            const int gn = bn * BN + wn * 64 + ni * 16;
            // 16x16 tile = 64 float4 quads; 2 per lane
#pragma unroll
            for (int e = lane; e < 64; e += 32) {
                int r = e >> 2, c4 = (e & 3) * 4;
                float4 v = *reinterpret_cast<const float4*>(&stage[r * 24 + c4]);
                float4 b = *reinterpret_cast<const float4*>(&bias[gn + c4]);
                v.x = (v.x + b.x) * scl; v.y = (v.y + b.y) * scl;
                v.z = (v.z + b.z) * scl; v.w = (v.w + b.w) * scl;
                *reinterpret_cast<float4*>(&g_qkv[(size_t)(gm + r) * N3C + gn + c4]) = v;
            }
            __syncwarp();
        }
    }
}

// ---------------- Attention: one CTA per window (49 tokens), all fp32 ----------------
// smem: Qt[512][52] (later aliased by ST = P^T), KV (K^T then V), S [49][52].
#define KQSTR 52
#define VSTR  516
#define QT_F  (512 * KQSTR)
#define S_OFF (2 * QT_F)
#define ATT_SMEM_BYTES ((2 * QT_F + WTOK * KQSTR) * 4)  // 223184

__global__ void __launch_bounds__(512) attn_kernel(float* __restrict__ out) {
    extern __shared__ float sm[];
    float* Qt = sm;            // q transposed [c][i] (pre-scaled); dead after QK -> reused as ST
    float* KV = sm + QT_F;     // k transposed [c][j]; later v natural [j][c]
    float* S  = sm + S_OFF;    // logits [49][52]
    float* ST = sm;            // probabilities transposed [j][i] (aliases Qt)

    const int w = blockIdx.x;
    const size_t base = (size_t)w * WTOK;
    const int tid = threadIdx.x;
    const int lane = tid & 31;

    // Load Q (pre-scaled) and K, both transposed [c][token]
    for (int idx = tid; idx < WTOK * DIMC; idx += 512) {
        int i = idx >> 9, c = idx & 511;
        const float* row = g_qkv + (base + i) * N3C;
        Qt[c * KQSTR + i] = row[c];
        KV[c * KQSTR + i] = row[512 + c];
    }
    __syncthreads();

    // ---- S = q @ k^T: 91 tiles (13 ig x 7 jg) of 4x8, x4 channel-chunks = 364 threads ----
    if (tid < 364) {
        const int tile = tid >> 2, cq = tid & 3;
        const int ig = tile % 13, jg = tile / 13;
        const int i0 = ig * 4, j0 = jg * 8;
        float acc[4][8];
#pragma unroll
        for (int r = 0; r < 4; r++)
#pragma unroll
            for (int s = 0; s < 8; s++) acc[r][s] = 0.f;

        const int cbeg = cq * 128;
        for (int c = cbeg; c < cbeg + 128; c++) {
            const float* qr = &Qt[c * KQSTR];
            const float* kr = &KV[c * KQSTR];
            float4 qv = *reinterpret_cast<const float4*>(&qr[i0]);
            float4 ka = *reinterpret_cast<const float4*>(&kr[j0]);
            float4 kb = *reinterpret_cast<const float4*>(&kr[j0 + 4]);
            float qs[4] = {qv.x, qv.y, qv.z, qv.w};
            float ks[8] = {ka.x, ka.y, ka.z, ka.w, kb.x, kb.y, kb.z, kb.w};
#pragma unroll
            for (int r = 0; r < 4; r++)
#pragma unroll
                for (int s = 0; s < 8; s++)
                    acc[r][s] += qs[r] * ks[s];
        }
        // reduce the 4 channel-chunks (adjacent lanes) via shfl
        const unsigned gmask = 0xFu << (lane & 28);
#pragma unroll
        for (int r = 0; r < 4; r++)
#pragma unroll
            for (int s = 0; s < 8; s++) {
                float v = acc[r][s];
                v += __shfl_xor_sync(gmask, v, 1);
                v += __shfl_xor_sync(gmask, v, 2);
                acc[r][s] = v;
            }
        if (cq == 0) {
#pragma unroll
            for (int r = 0; r < 4; r++) {
                if (i0 + r < WTOK) {
#pragma unroll
                    for (int s = 0; s < 8; s++)
                        if (j0 + s < WTOK)
                            S[(i0 + r) * KQSTR + j0 + s] = acc[r][s];
                }
            }
        }
    }
    __syncthreads();

    // ---- V load (overwrites K^T region) + softmax (writes P^T into ST, aliasing Qt) ----
    for (int idx = tid; idx < WTOK * (DIMC / 4); idx += 512) {
        int i = idx >> 7, c4 = idx & 127;
        float4 v = *reinterpret_cast<const float4*>(&g_qkv[(base + i) * N3C + 1024 + c4 * 4]);
        *reinterpret_cast<float4*>(&KV[i * VSTR + c4 * 4]) = v;
    }
    if (tid < WTOK) {
        float* Sr = &S[tid * KQSTR];
        float m = -1e30f;
        for (int j = 0; j < WTOK; j++) m = fmaxf(m, Sr[j]);
        float s = 0.f;
        float e[WTOK];
        for (int j = 0; j < WTOK; j++) { e[j] = __expf(Sr[j] - m); s += e[j]; }
        float inv = 1.0f / s;
        for (int j = 0; j < WTOK; j++) ST[j * KQSTR + tid] = e[j] * inv;
    }
    __syncthreads();

    // ---- out = P @ V: tiles 4 rows x 8 cols: 13 x 64 = 832 tasks ----
    for (int t = tid; t < 832; t += 512) {
        const int cc = t & 63, ig = t >> 6;
        const int i0 = ig * 4, c = cc * 8;
        float acc[4][8];
#pragma unroll
        for (int r = 0; r < 4; r++)
#pragma unroll
            for (int s = 0; s < 8; s++) acc[r][s] = 0.f;

#pragma unroll 7
        for (int j = 0; j < WTOK; j++) {
            float4 p  = *reinterpret_cast<const float4*>(&ST[j * KQSTR + i0]);
            float4 va = *reinterpret_cast<const float4*>(&KV[j * VSTR + c]);
            float4 vb = *reinterpret_cast<const float4*>(&KV[j * VSTR + c + 4]);
            float ps[4] = {p.x, p.y, p.z, p.w};
            float vs[8] = {va.x, va.y, va.z, va.w, vb.x, vb.y, vb.z, vb.w};
#pragma unroll
            for (int r = 0; r < 4; r++)
#pragma unroll
                for (int s = 0; s < 8; s++)
                    acc[r][s] += ps[r] * vs[s];
        }
#pragma unroll
        for (int r = 0; r < 4; r++) {
            if (i0 + r < WTOK) {
                float* orow = &out[(base + i0 + r) * DIMC + c];
                *reinterpret_cast<float4*>(orow) =
                    make_float4(acc[r][0], acc[r][1], acc[r][2], acc[r][3]);
                *reinterpret_cast<float4*>(orow + 4) =
                    make_float4(acc[r][4], acc[r][5], acc[r][6], acc[r][7]);
            }
        }
    }
}

// ---------------- launch ----------------
extern "C" void kernel_launch(void* const* d_in, const int* in_sizes, int n_in,
                              void* d_out, int out_size) {
    const float* x    = (const float*)d_in[0];
    // d_in[1] (x_all) is unused by the reference computation.
    const float* W    = (const float*)d_in[2];
    const float* bqkv = (const float*)d_in[3];
    float* out = (float*)d_out;
    (void)in_sizes; (void)n_in; (void)out_size;

    {
        int n4 = (MROWS * DIMC) / 4;  // 12,845,056
        conv_x_kernel<<<(n4 + 255) / 256, 256>>>(x, n4);
    }
    {
        int n4 = (DIMC * N3C) / 4;    // 196,608
        conv_w_kernel<<<(n4 + 255) / 256, 256>>>(W, n4);
    }
    {
        cudaFuncSetAttribute(qkv_gemm_kernel,
                             cudaFuncAttributeMaxDynamicSharedMemorySize,
                             GEMM_SMEM_BYTES);
        dim3 grid(N3C / BN, MROWS / BM);  // (12, 784): bn fastest for A-tile L2 reuse
        qkv_gemm_kernel<<<grid, 256, GEMM_SMEM_BYTES>>>(bqkv);
    }
    {
        cudaFuncSetAttribute(attn_kernel,
                             cudaFuncAttributeMaxDynamicSharedMemorySize,
                             ATT_SMEM_BYTES);
        attn_kernel<<<NWIN, 512, ATT_SMEM_BYTES>>>(out);
    }
}